// round 16
// baseline (speedup 1.0000x reference)
#include <cuda_runtime.h>
#include <cstdint>

// Problem constants
#define A_CLS 50
#define C_CL  1024
#define F_LIT 1180
#define B_SMP 512
#define AC    (A_CLS * C_CL)     // 51200 clauses
#define NW    37                 // ceil(1180/32) x-mask words (plain layout)

// Scratch (static __device__ globals — no runtime allocation)
// Plain bit layout: x word w, bit l = x[32w + l].
__device__ unsigned d_xbits[B_SMP][NW];   // full x masks (verify path)
__device__ unsigned d_x0[B_SMP];          // word 0 (fast screen)
__device__ float    d_votes[B_SMP * A_CLS];
__device__ unsigned d_done;               // completion ticket

// ---------------------------------------------------------------------------
// pack_x: one warp per sample row. R15's version was a 37-deep DEPENDENT
// LDG->ballot chain with only 3.5 warps/SM — ~15us of exposed latency that
// dominated the whole pipeline. Now: all 37 row words are loaded into
// registers first (37 independent LDGs, MLP=37, ONE latency exposure), then
// the ballots run back-to-back. Also zeroes votes + ticket.
// ---------------------------------------------------------------------------
__global__ void pack_x_kernel(const float* __restrict__ x) {
    int gtid = blockIdx.x * blockDim.x + threadIdx.x;
    int warp = gtid >> 5;
    int lane = threadIdx.x & 31;
    if (warp < B_SMP) {
        const float* row = x + (size_t)warp * F_LIT;
        float v[NW];
        #pragma unroll
        for (int w = 0; w < NW; w++) {
            int f = w * 32 + lane;
            v[w] = (f < F_LIT) ? __ldg(row + f) : 0.0f;   // independent LDGs
        }
        #pragma unroll
        for (int w = 0; w < NW; w++) {
            unsigned bits = __ballot_sync(0xFFFFFFFFu, v[w] > 0.5f);
            if (lane == 0) {
                d_xbits[warp][w] = bits;
                if (w == 0) d_x0[warp] = bits;
            }
        }
    }
    for (int i = gtid; i < B_SMP * A_CLS; i += gridDim.x * blockDim.x)
        d_votes[i] = 0.0f;
    if (gtid == 0) d_done = 0u;
}

// ---------------------------------------------------------------------------
// Screen + verify + (last block) output. One warp per EIGHT clauses.
//
// Screening on the first 32 literals (P(clean) = 2^-32 per eval) reads only
// 2 x 128 B per clause (26 MB incl. line splits) instead of 483 MB ta_state;
// that slice stays L2-resident across graph replays. 16 independent row
// loads up front (MLP=16), 16 ballots, then a fused screen: per x-word
// iteration 1 LDS.128 + 8 clauses x (4 LOP3 + min-tree), all collapsed into
// one `grand` min and ONE branch per warp. 6400 warps / 800 blocks ~ 1 wave.
// Candidates (~0.006 expected per launch) recompute + verify exactly against
// the raw ta rows; votes via atomicAdd (~never); ticket lets the last block
// clip and write the output.
// ---------------------------------------------------------------------------
__global__ __launch_bounds__(256, 4)
void screen_kernel(const float* __restrict__ ta,
                   const float* __restrict__ clause_sign,
                   const int*   __restrict__ tptr,
                   float*       __restrict__ out) {
    __shared__ __align__(16) unsigned sx0[B_SMP];
    __shared__ bool sLast;

    // all 512 word-0 x masks (2 KB), cooperative coalesced load
    for (int i = threadIdx.x; i < B_SMP / 4; i += blockDim.x)
        reinterpret_cast<uint4*>(sx0)[i] = reinterpret_cast<const uint4*>(d_x0)[i];
    __syncthreads();

    int wid  = blockIdx.x * (blockDim.x >> 5) + (threadIdx.x >> 5);
    int lane = threadIdx.x & 31;
    int ac0  = wid * 8;                       // 6400 warps x 8 clauses = AC

    // 16 independent 128B row loads (first 32 literals of pos/neg rows)
    float pv[8], nv[8];
    #pragma unroll
    for (int k = 0; k < 8; k++) {
        const float* pos = ta + (size_t)(ac0 + k) * 2 * F_LIT;
        pv[k] = __ldg(pos + lane);
        nv[k] = __ldg(pos + F_LIT + lane);
    }
    unsigned p0[8], n0[8];
    #pragma unroll
    for (int k = 0; k < 8; k++) {
        p0[k] = __ballot_sync(0xFFFFFFFFu, pv[k] > 16.0f);
        n0[k] = __ballot_sync(0xFFFFFFFFu, nv[k] > 16.0f);
    }

    // fused screen: 4 x-word iters x 32 LOP3, one grand min, one branch
    unsigned grand = 0xFFFFFFFFu;
    #pragma unroll
    for (int r = 0; r < 4; r++) {
        uint4 x = *reinterpret_cast<const uint4*>(&sx0[(r * 32 + lane) * 4]);
        #pragma unroll
        for (int k = 0; k < 8; k++) {
            unsigned v0 = (p0[k] & ~x.x) | (n0[k] & x.x);   // 1 LOP3 each
            unsigned v1 = (p0[k] & ~x.y) | (n0[k] & x.y);
            unsigned v2 = (p0[k] & ~x.z) | (n0[k] & x.z);
            unsigned v3 = (p0[k] & ~x.w) | (n0[k] & x.w);
            grand = min(grand, min(min(v0, v1), min(v2, v3)));
        }
    }

    // cold path: recompute per-eval results, verify exactly vs raw ta
    if (grand == 0u) {                        // P ~ 4e-10 per lane
        #pragma unroll 1
        for (int r = 0; r < 4; r++) {
            uint4 x = *reinterpret_cast<const uint4*>(&sx0[(r * 32 + lane) * 4]);
            unsigned xs[4] = {x.x, x.y, x.z, x.w};
            #pragma unroll 1
            for (int k = 0; k < 8; k++) {
                int ac = ac0 + k;
                const float* pos = ta + (size_t)ac * 2 * F_LIT;
                const float* neg = pos + F_LIT;
                #pragma unroll 1
                for (int j = 0; j < 4; j++) {
                    if (((p0[k] & ~xs[j]) | (n0[k] & xs[j])) != 0u) continue;
                    int b = (r * 32 + lane) * 4 + j;
                    bool fire = true;
                    #pragma unroll 1
                    for (int w = 0; w < NW && fire; w++) {
                        unsigned xw = d_xbits[b][w];
                        int base = w * 32;
                        int lim  = (F_LIT - base < 32) ? (F_LIT - base) : 32;
                        #pragma unroll 1
                        for (int l = 0; l < lim; l++) {
                            bool xb = (xw >> l) & 1u;
                            if ((__ldg(pos + base + l) > 16.0f && !xb) ||
                                (__ldg(neg + base + l) > 16.0f &&  xb)) {
                                fire = false; break;
                            }
                        }
                    }
                    if (fire)
                        atomicAdd(&d_votes[b * A_CLS + (ac >> 10)],
                                  __ldg(&clause_sign[ac]));
                }
            }
        }
    }

    // completion ticket; last block clips votes and writes the output
    __syncthreads();
    if (threadIdx.x == 0) {
        __threadfence();                         // release votes
        unsigned t = atomicAdd(&d_done, 1u);
        sLast = (t == gridDim.x - 1);
    }
    __syncthreads();
    if (sLast) {
        __threadfence();                         // acquire votes
        // T dtype is ambiguous (python int in the reference): small
        // non-negative bit-patterns -> int32, anything else -> float32 bits.
        int ti = *tptr;
        float T = (ti >= 0 && ti < (1 << 23)) ? (float)ti : __int_as_float(ti);
        for (int i = threadIdx.x; i < B_SMP * A_CLS; i += blockDim.x) {
            float v = d_votes[i];                // layout [B, A] == out
            out[i] = fminf(fmaxf(v, -T), T);
        }
    }
}

// ---------------------------------------------------------------------------
extern "C" void kernel_launch(void* const* d_in, const int* in_sizes, int n_in,
                              void* d_out, int out_size) {
    const float* x  = (const float*)d_in[0];  // binary_features [512, 1180]
    const float* ta = (const float*)d_in[1];  // ta_state [50, 1024, 2, 1180]
    const float* cs = (const float*)d_in[2];  // clause_sign [50, 1024]
    const int*   Tp = (const int*)  d_in[3];  // T scalar

    (void)in_sizes; (void)n_in; (void)out_size;

    // 1. pack x masks (MLP=37, one latency exposure) + zero votes/ticket
    pack_x_kernel<<<64, 256>>>(x);
    // 2. screen (26 MB ta slice, 8 clauses/warp) + exact verify + output
    screen_kernel<<<AC / 8 / 8, 256>>>(ta, cs, Tp, (float*)d_out);
}